// round 2
// baseline (speedup 1.0000x reference)
#include <cuda_runtime.h>
#include <math.h>

#define C      128
#define NPTS   32768
#define KP     20
#define EPSF   1e-7f
#define TPB    256
#define ITER   16
#define NBPC   8            // blocks per channel in k_main: 8*256*16 = 32768
#define NBLK   (C*NBPC)     // 1024

// ---------------- constant-bank weights ----------------
__constant__ float cWx1[64], cbx1[8],  cWx2[8],  cbx2[1];
__constant__ float cWe1[64], cbe1[8],  cWe2[8],  cbe2[1];
__constant__ float cWf1[64], cbf1[8],  cWf2[160], cbf2[20];

// ---------------- device scratch (no allocations allowed) ----------------
__device__ float g_xs[C * NPTS];
__device__ float g_es[C * NPTS];
__device__ float g_yp[C * KP];
__device__ float g_pmin[NBLK], g_pmax[NBLK], g_psum[NBLK], g_psum2[NBLK];
__device__ float g_minv[C], g_invr[C];
__device__ float g_mean, g_scale;

// fast tanh: (e^{2x}-1)/(e^{2x}+1), abs err ~1e-7
__device__ __forceinline__ float ftanh(float x) {
    float xc = fminf(fmaxf(x, -15.f), 15.f);
    float t  = __expf(2.f * xc);
    return __fdividef(t - 1.f, t + 1.f);
}

// ---------------- kernel 1: yp (pts MLP + sort + direction) ----------------
__global__ void k_yp(const float* __restrict__ zf,
                     const unsigned char* __restrict__ dirraw) {
    int c = threadIdx.x;          // 128 threads
    __shared__ int s_isbool;
    if (c == 0) {
        // If directions were serialized as int32, every byte at index %4 != 0
        // is zero. If serialized as bool bytes, random 0/1 appear everywhere.
        int f = 0;
        for (int i = 0; i < 128; i++) if (i & 3) f |= dirraw[i];
        s_isbool = (f != 0);
    }
    __syncthreads();
    if (c >= C) return;

    float z[8];
#pragma unroll
    for (int i = 0; i < 8; i++) z[i] = zf[c * 8 + i];

    float h[8];
#pragma unroll
    for (int j = 0; j < 8; j++) {
        float a = cbf1[j];
#pragma unroll
        for (int k = 0; k < 8; k++) a = fmaf(z[k], cWf1[k * 8 + j], a);
        h[j] = tanhf(a);
    }
    float p[KP];
#pragma unroll
    for (int j = 0; j < KP; j++) {
        float a = cbf2[j];
#pragma unroll
        for (int k = 0; k < 8; k++) a = fmaf(h[k], cWf2[k * 20 + j], a);
        p[j] = tanhf(a);
    }
    // insertion sort ascending (20 elements)
    for (int i = 1; i < KP; i++) {
        float key = p[i];
        int j = i - 1;
        while (j >= 0 && p[j] > key) { p[j + 1] = p[j]; j--; }
        p[j + 1] = key;
    }
    bool d = s_isbool ? (dirraw[c] != 0)
                      : (((const int*)dirraw)[c] != 0);
    for (int j = 0; j < KP; j++)
        g_yp[c * KP + j] = d ? p[j] : p[KP - 1 - j];
}

// ---------------- kernel 2: main MLPs + partial reductions ----------------
__device__ __forceinline__ float mlp_x(const float zv[8]) {
    float acc = cbx2[0];
#pragma unroll
    for (int j = 0; j < 8; j++) {
        float hh = cbx1[j];
#pragma unroll
        for (int k = 0; k < 8; k++) hh = fmaf(zv[k], cWx1[k * 8 + j], hh);
        acc = fmaf(ftanh(hh), cWx2[j], acc);
    }
    return ftanh(acc);
}
__device__ __forceinline__ float mlp_e(const float zv[8]) {
    float acc = cbe2[0];
#pragma unroll
    for (int j = 0; j < 8; j++) {
        float hh = cbe1[j];
#pragma unroll
        for (int k = 0; k < 8; k++) hh = fmaf(zv[k], cWe1[k * 8 + j], hh);
        acc = fmaf(ftanh(hh), cWe2[j], acc);
    }
    return ftanh(acc);
}

__global__ __launch_bounds__(TPB) void k_main(const float* __restrict__ zx,
                                              const float* __restrict__ ze) {
    int c    = blockIdx.y;
    int base = blockIdx.x * (TPB * ITER) + threadIdx.x;
    int row  = c * NPTS;
    const float4* zx4 = (const float4*)zx;
    const float4* ze4 = (const float4*)ze;

    float mn = 1e30f, mx = -1e30f, s = 0.f, s2 = 0.f;

#pragma unroll 2
    for (int k = 0; k < ITER; k++) {
        int n   = base + k * TPB;
        int idx = row + n;

        float4 a = zx4[idx * 2], b = zx4[idx * 2 + 1];
        float zv[8] = {a.x, a.y, a.z, a.w, b.x, b.y, b.z, b.w};
        float xv = mlp_x(zv);
        g_xs[idx] = xv;
        mn = fminf(mn, xv);
        mx = fmaxf(mx, xv);

        a = ze4[idx * 2]; b = ze4[idx * 2 + 1];
        float wv[8] = {a.x, a.y, a.z, a.w, b.x, b.y, b.z, b.w};
        float ev = mlp_e(wv);
        g_es[idx] = ev;
        s += ev;
        s2 = fmaf(ev, ev, s2);
    }

    // deterministic block reduction
    unsigned lane = threadIdx.x & 31u, warp = threadIdx.x >> 5;
#pragma unroll
    for (int off = 16; off; off >>= 1) {
        mn = fminf(mn, __shfl_down_sync(0xffffffffu, mn, off));
        mx = fmaxf(mx, __shfl_down_sync(0xffffffffu, mx, off));
        s  += __shfl_down_sync(0xffffffffu, s,  off);
        s2 += __shfl_down_sync(0xffffffffu, s2, off);
    }
    __shared__ float smn[8], smx[8], ss[8], ss2[8];
    if (lane == 0) { smn[warp] = mn; smx[warp] = mx; ss[warp] = s; ss2[warp] = s2; }
    __syncthreads();
    if (threadIdx.x == 0) {
        mn = smn[0]; mx = smx[0]; s = ss[0]; s2 = ss2[0];
#pragma unroll
        for (int w = 1; w < 8; w++) {
            mn = fminf(mn, smn[w]); mx = fmaxf(mx, smx[w]);
            s += ss[w]; s2 += ss2[w];
        }
        int pb = blockIdx.y * gridDim.x + blockIdx.x;   // c*NBPC + blk
        g_pmin[pb] = mn; g_pmax[pb] = mx;
        g_psum[pb] = s;  g_psum2[pb] = s2;
    }
}

// ---------------- kernel 3: finalize stats ----------------
__global__ void k_stats() {
    int t = threadIdx.x;   // 256 threads, 1 block
    if (t < C) {
        float mn = 1e30f, mx = -1e30f;
#pragma unroll
        for (int i = 0; i < NBPC; i++) {
            mn = fminf(mn, g_pmin[t * NBPC + i]);
            mx = fmaxf(mx, g_pmax[t * NBPC + i]);
        }
        g_minv[t] = mn;
        g_invr[t] = 1.f / (mx - mn);
    }
    float s = 0.f, s2 = 0.f;
    for (int i = t; i < NBLK; i += blockDim.x) { s += g_psum[i]; s2 += g_psum2[i]; }
#pragma unroll
    for (int off = 16; off; off >>= 1) {
        s  += __shfl_down_sync(0xffffffffu, s,  off);
        s2 += __shfl_down_sync(0xffffffffu, s2, off);
    }
    __shared__ float rs[8], rs2[8];
    if ((t & 31) == 0) { rs[t >> 5] = s; rs2[t >> 5] = s2; }
    __syncthreads();
    if (t == 0) {
        double S = 0.0, S2 = 0.0;
        for (int w = 0; w < 8; w++) { S += rs[w]; S2 += rs2[w]; }
        double M    = (double)C * (double)NPTS;
        double mean = S / M;
        double var  = (S2 - S * S / M) / (M - 1.0);
        g_mean  = (float)mean;
        g_scale = (float)(0.1 / sqrt(var));
    }
}

// ---------------- kernel 4: calibrate + noise, [C,N]->[N,C] transpose ----------------
__global__ __launch_bounds__(TPB) void k_final(float* __restrict__ y) {
    __shared__ float s_yp[C * KP];
    __shared__ float s_min[C], s_inv[C];
    __shared__ float sx[C][33];
    __shared__ float se[C][33];

    int tid = threadIdx.x;
    for (int i = tid; i < C * KP; i += TPB) s_yp[i] = g_yp[i];
    if (tid < C) { s_min[tid] = g_minv[tid]; s_inv[tid] = g_invr[tid]; }

    int n0 = blockIdx.x * 32;
    int warp = tid >> 5, lane = tid & 31;
#pragma unroll
    for (int c = warp; c < C; c += 8) {
        sx[c][lane] = g_xs[c * NPTS + n0 + lane];
        se[c][lane] = g_es[c * NPTS + n0 + lane];
    }
    __syncthreads();

    float mean  = g_mean, scale = g_scale;
    const float step = 1.0f / 19.0f;
    const float rden = 1.0f / (step + EPSF);

    int c  = tid & (C - 1);
    int nh = tid >> 7;        // 0 or 1
#pragma unroll
    for (int p = 0; p < 16; p++) {
        int nl = p * 2 + nh;
        float xv = (sx[c][nl] - s_min[c]) * s_inv[c];
        int seg = (int)ceilf(xv * 19.0f) - 1;
        seg = max(0, min(18, seg));
        float y0 = s_yp[c * KP + seg];
        float y1 = s_yp[c * KP + seg + 1];
        float val = fmaf((xv - (float)seg * step) * rden, y1 - y0, y0);
        y[(n0 + nl) * C + c] = fmaf(se[c][nl] - mean, scale, val);
    }
}

// ---------------- launch ----------------
extern "C" void kernel_launch(void* const* d_in, const int* in_sizes, int n_in,
                              void* d_out, int out_size) {
    const float* zf = (const float*)d_in[0];
    const float* zx = (const float*)d_in[1];
    const float* ze = (const float*)d_in[2];

    cudaMemcpyToSymbolAsync(cWx1, d_in[3],  64 * 4, 0, cudaMemcpyDeviceToDevice, 0);
    cudaMemcpyToSymbolAsync(cbx1, d_in[4],   8 * 4, 0, cudaMemcpyDeviceToDevice, 0);
    cudaMemcpyToSymbolAsync(cWx2, d_in[5],   8 * 4, 0, cudaMemcpyDeviceToDevice, 0);
    cudaMemcpyToSymbolAsync(cbx2, d_in[6],   1 * 4, 0, cudaMemcpyDeviceToDevice, 0);
    cudaMemcpyToSymbolAsync(cWe1, d_in[7],  64 * 4, 0, cudaMemcpyDeviceToDevice, 0);
    cudaMemcpyToSymbolAsync(cbe1, d_in[8],   8 * 4, 0, cudaMemcpyDeviceToDevice, 0);
    cudaMemcpyToSymbolAsync(cWe2, d_in[9],   8 * 4, 0, cudaMemcpyDeviceToDevice, 0);
    cudaMemcpyToSymbolAsync(cbe2, d_in[10],  1 * 4, 0, cudaMemcpyDeviceToDevice, 0);
    cudaMemcpyToSymbolAsync(cWf1, d_in[11], 64 * 4, 0, cudaMemcpyDeviceToDevice, 0);
    cudaMemcpyToSymbolAsync(cbf1, d_in[12],  8 * 4, 0, cudaMemcpyDeviceToDevice, 0);
    cudaMemcpyToSymbolAsync(cWf2, d_in[13], 160 * 4, 0, cudaMemcpyDeviceToDevice, 0);
    cudaMemcpyToSymbolAsync(cbf2, d_in[14], 20 * 4, 0, cudaMemcpyDeviceToDevice, 0);

    const unsigned char* dirs = (const unsigned char*)d_in[15];

    k_yp<<<1, 128>>>(zf, dirs);
    dim3 g2(NBPC, C);
    k_main<<<g2, TPB>>>(zx, ze);
    k_stats<<<1, 256>>>();
    k_final<<<NPTS / 32, TPB>>>((float*)d_out);
}

// round 3
// speedup vs baseline: 1.0150x; 1.0150x over previous
#include <cuda_runtime.h>
#include <math.h>

#define C      128
#define NPTS   32768
#define KP     20
#define EPSF   1e-7f
#define TPB    256
#define ITER   16
#define NBPC   8            // blocks per channel in k_main: 8*256*16 = 32768
#define NBLK   (C*NBPC)     // 1024

// ---------------- constant-bank weights ----------------
__constant__ float cWx1[64], cbx1[8],  cWx2[8],  cbx2[1];
__constant__ float cWe1[64], cbe1[8],  cWe2[8],  cbe2[1];
__constant__ float cWf1[64], cbf1[8],  cWf2[160], cbf2[20];

// ---------------- device scratch (no allocations allowed) ----------------
__device__ float g_xs[C * NPTS];
__device__ float g_es[C * NPTS];
__device__ float g_yp[C * KP];
__device__ float g_pmin[NBLK], g_pmax[NBLK], g_psum[NBLK], g_psum2[NBLK];
__device__ float g_minv[C], g_invr[C];
__device__ float g_mean, g_scale;

// fast tanh: (e^{2x}-1)/(e^{2x}+1), abs err ~1e-7
__device__ __forceinline__ float ftanh(float x) {
    float xc = fminf(fmaxf(x, -15.f), 15.f);
    float t  = __expf(2.f * xc);
    return __fdividef(t - 1.f, t + 1.f);
}

// ---------------- kernel 1: yp (pts MLP + sort + direction) ----------------
__global__ void k_yp(const float* __restrict__ zf,
                     const unsigned char* __restrict__ dirraw) {
    int c = threadIdx.x;          // 128 threads
    __shared__ int s_isbool;
    if (c == 0) {
        // If directions were serialized as int32, every byte at index %4 != 0
        // is zero. If serialized as bool bytes, random 0/1 appear everywhere.
        int f = 0;
        for (int i = 0; i < 128; i++) if (i & 3) f |= dirraw[i];
        s_isbool = (f != 0);
    }
    __syncthreads();
    if (c >= C) return;

    float z[8];
#pragma unroll
    for (int i = 0; i < 8; i++) z[i] = zf[c * 8 + i];

    float h[8];
#pragma unroll
    for (int j = 0; j < 8; j++) {
        float a = cbf1[j];
#pragma unroll
        for (int k = 0; k < 8; k++) a = fmaf(z[k], cWf1[k * 8 + j], a);
        h[j] = tanhf(a);
    }
    float p[KP];
#pragma unroll
    for (int j = 0; j < KP; j++) {
        float a = cbf2[j];
#pragma unroll
        for (int k = 0; k < 8; k++) a = fmaf(h[k], cWf2[k * 20 + j], a);
        p[j] = tanhf(a);
    }
    // insertion sort ascending (20 elements)
    for (int i = 1; i < KP; i++) {
        float key = p[i];
        int j = i - 1;
        while (j >= 0 && p[j] > key) { p[j + 1] = p[j]; j--; }
        p[j + 1] = key;
    }
    bool d = s_isbool ? (dirraw[c] != 0)
                      : (((const int*)dirraw)[c] != 0);
    for (int j = 0; j < KP; j++)
        g_yp[c * KP + j] = d ? p[j] : p[KP - 1 - j];
}

// ---------------- kernel 2: main MLPs + partial reductions ----------------
__device__ __forceinline__ float mlp_x(const float zv[8]) {
    float acc = cbx2[0];
#pragma unroll
    for (int j = 0; j < 8; j++) {
        float hh = cbx1[j];
#pragma unroll
        for (int k = 0; k < 8; k++) hh = fmaf(zv[k], cWx1[k * 8 + j], hh);
        acc = fmaf(ftanh(hh), cWx2[j], acc);
    }
    return ftanh(acc);
}
__device__ __forceinline__ float mlp_e(const float zv[8]) {
    float acc = cbe2[0];
#pragma unroll
    for (int j = 0; j < 8; j++) {
        float hh = cbe1[j];
#pragma unroll
        for (int k = 0; k < 8; k++) hh = fmaf(zv[k], cWe1[k * 8 + j], hh);
        acc = fmaf(ftanh(hh), cWe2[j], acc);
    }
    return ftanh(acc);
}

__global__ __launch_bounds__(TPB) void k_main(const float* __restrict__ zx,
                                              const float* __restrict__ ze) {
    int c    = blockIdx.y;
    int base = blockIdx.x * (TPB * ITER) + threadIdx.x;
    int row  = c * NPTS;
    const float4* zx4 = (const float4*)zx;
    const float4* ze4 = (const float4*)ze;

    float mn = 1e30f, mx = -1e30f, s = 0.f, s2 = 0.f;

#pragma unroll 2
    for (int k = 0; k < ITER; k++) {
        int n   = base + k * TPB;
        int idx = row + n;

        float4 a = zx4[idx * 2], b = zx4[idx * 2 + 1];
        float zv[8] = {a.x, a.y, a.z, a.w, b.x, b.y, b.z, b.w};
        float xv = mlp_x(zv);
        g_xs[idx] = xv;
        mn = fminf(mn, xv);
        mx = fmaxf(mx, xv);

        a = ze4[idx * 2]; b = ze4[idx * 2 + 1];
        float wv[8] = {a.x, a.y, a.z, a.w, b.x, b.y, b.z, b.w};
        float ev = mlp_e(wv);
        g_es[idx] = ev;
        s += ev;
        s2 = fmaf(ev, ev, s2);
    }

    // deterministic block reduction
    unsigned lane = threadIdx.x & 31u, warp = threadIdx.x >> 5;
#pragma unroll
    for (int off = 16; off; off >>= 1) {
        mn = fminf(mn, __shfl_down_sync(0xffffffffu, mn, off));
        mx = fmaxf(mx, __shfl_down_sync(0xffffffffu, mx, off));
        s  += __shfl_down_sync(0xffffffffu, s,  off);
        s2 += __shfl_down_sync(0xffffffffu, s2, off);
    }
    __shared__ float smn[8], smx[8], ss[8], ss2[8];
    if (lane == 0) { smn[warp] = mn; smx[warp] = mx; ss[warp] = s; ss2[warp] = s2; }
    __syncthreads();
    if (threadIdx.x == 0) {
        mn = smn[0]; mx = smx[0]; s = ss[0]; s2 = ss2[0];
#pragma unroll
        for (int w = 1; w < 8; w++) {
            mn = fminf(mn, smn[w]); mx = fmaxf(mx, smx[w]);
            s += ss[w]; s2 += ss2[w];
        }
        int pb = blockIdx.y * gridDim.x + blockIdx.x;   // c*NBPC + blk
        g_pmin[pb] = mn; g_pmax[pb] = mx;
        g_psum[pb] = s;  g_psum2[pb] = s2;
    }
}

// ---------------- kernel 3: finalize stats ----------------
__global__ void k_stats() {
    int t = threadIdx.x;   // 256 threads, 1 block
    if (t < C) {
        float mn = 1e30f, mx = -1e30f;
#pragma unroll
        for (int i = 0; i < NBPC; i++) {
            mn = fminf(mn, g_pmin[t * NBPC + i]);
            mx = fmaxf(mx, g_pmax[t * NBPC + i]);
        }
        g_minv[t] = mn;
        g_invr[t] = 1.f / (mx - mn);
    }
    float s = 0.f, s2 = 0.f;
    for (int i = t; i < NBLK; i += blockDim.x) { s += g_psum[i]; s2 += g_psum2[i]; }
#pragma unroll
    for (int off = 16; off; off >>= 1) {
        s  += __shfl_down_sync(0xffffffffu, s,  off);
        s2 += __shfl_down_sync(0xffffffffu, s2, off);
    }
    __shared__ float rs[8], rs2[8];
    if ((t & 31) == 0) { rs[t >> 5] = s; rs2[t >> 5] = s2; }
    __syncthreads();
    if (t == 0) {
        double S = 0.0, S2 = 0.0;
        for (int w = 0; w < 8; w++) { S += rs[w]; S2 += rs2[w]; }
        double M    = (double)C * (double)NPTS;
        double mean = S / M;
        double var  = (S2 - S * S / M) / (M - 1.0);
        g_mean  = (float)mean;
        g_scale = (float)(0.1 / sqrt(var));
    }
}

// ---------------- kernel 4: calibrate + noise, [C,N]->[N,C] transpose ----------------
__global__ __launch_bounds__(TPB) void k_final(float* __restrict__ y) {
    __shared__ float s_yp[C * KP];
    __shared__ float s_min[C], s_inv[C];
    __shared__ float sx[C][33];
    __shared__ float se[C][33];

    int tid = threadIdx.x;
    for (int i = tid; i < C * KP; i += TPB) s_yp[i] = g_yp[i];
    if (tid < C) { s_min[tid] = g_minv[tid]; s_inv[tid] = g_invr[tid]; }

    int n0 = blockIdx.x * 32;
    int warp = tid >> 5, lane = tid & 31;
#pragma unroll
    for (int c = warp; c < C; c += 8) {
        sx[c][lane] = g_xs[c * NPTS + n0 + lane];
        se[c][lane] = g_es[c * NPTS + n0 + lane];
    }
    __syncthreads();

    float mean  = g_mean, scale = g_scale;
    const float step = 1.0f / 19.0f;
    const float rden = 1.0f / (step + EPSF);

    int c  = tid & (C - 1);
    int nh = tid >> 7;        // 0 or 1
#pragma unroll
    for (int p = 0; p < 16; p++) {
        int nl = p * 2 + nh;
        float xv = (sx[c][nl] - s_min[c]) * s_inv[c];
        int seg = (int)ceilf(xv * 19.0f) - 1;
        seg = max(0, min(18, seg));
        float y0 = s_yp[c * KP + seg];
        float y1 = s_yp[c * KP + seg + 1];
        float val = fmaf((xv - (float)seg * step) * rden, y1 - y0, y0);
        y[(n0 + nl) * C + c] = fmaf(se[c][nl] - mean, scale, val);
    }
}

// ---------------- launch ----------------
extern "C" void kernel_launch(void* const* d_in, const int* in_sizes, int n_in,
                              void* d_out, int out_size) {
    const float* zf = (const float*)d_in[0];
    const float* zx = (const float*)d_in[1];
    const float* ze = (const float*)d_in[2];

    cudaMemcpyToSymbolAsync(cWx1, d_in[3],  64 * 4, 0, cudaMemcpyDeviceToDevice, 0);
    cudaMemcpyToSymbolAsync(cbx1, d_in[4],   8 * 4, 0, cudaMemcpyDeviceToDevice, 0);
    cudaMemcpyToSymbolAsync(cWx2, d_in[5],   8 * 4, 0, cudaMemcpyDeviceToDevice, 0);
    cudaMemcpyToSymbolAsync(cbx2, d_in[6],   1 * 4, 0, cudaMemcpyDeviceToDevice, 0);
    cudaMemcpyToSymbolAsync(cWe1, d_in[7],  64 * 4, 0, cudaMemcpyDeviceToDevice, 0);
    cudaMemcpyToSymbolAsync(cbe1, d_in[8],   8 * 4, 0, cudaMemcpyDeviceToDevice, 0);
    cudaMemcpyToSymbolAsync(cWe2, d_in[9],   8 * 4, 0, cudaMemcpyDeviceToDevice, 0);
    cudaMemcpyToSymbolAsync(cbe2, d_in[10],  1 * 4, 0, cudaMemcpyDeviceToDevice, 0);
    cudaMemcpyToSymbolAsync(cWf1, d_in[11], 64 * 4, 0, cudaMemcpyDeviceToDevice, 0);
    cudaMemcpyToSymbolAsync(cbf1, d_in[12],  8 * 4, 0, cudaMemcpyDeviceToDevice, 0);
    cudaMemcpyToSymbolAsync(cWf2, d_in[13], 160 * 4, 0, cudaMemcpyDeviceToDevice, 0);
    cudaMemcpyToSymbolAsync(cbf2, d_in[14], 20 * 4, 0, cudaMemcpyDeviceToDevice, 0);

    const unsigned char* dirs = (const unsigned char*)d_in[15];

    k_yp<<<1, 128>>>(zf, dirs);
    dim3 g2(NBPC, C);
    k_main<<<g2, TPB>>>(zx, ze);
    k_stats<<<1, 256>>>();
    k_final<<<NPTS / 32, TPB>>>((float*)d_out);
}